// round 2
// baseline (speedup 1.0000x reference)
#include <cuda_runtime.h>
#include <mma.h>

using namespace nvcuda;

#define T_      8
#define H_      64
#define W_      64
#define C_      256
#define HEADS_  8
#define HD_     32
#define WS_     7
#define NPIX    (T_ * H_ * W_)          // 32768
#define M_      NPIX
#define N_      512
#define K_      256
#define NS_     (3 * WS_ * WS_)         // 147 keys per pixel
#define SCALE_  0.17677669529663687f    // 32^-0.5

// 64 MB scratch for projected q|k rows: [pix][512] (q = m<256, k = m>=256)
__device__ float g_qk[(size_t)NPIX * N_];

// ---------------------------------------------------------------------------
// GEMM: qk[m, n] = sum_k x[m, k] * W_qk[n, k]    (tf32 WMMA, fp32 accum)
// ---------------------------------------------------------------------------
#define BM 64
#define BN 64
#define BK 32
#define LDS 40   // padded leading dim (multiple of 8 floats)

__global__ void __launch_bounds__(256) gemm_qk_kernel(
    const float* __restrict__ x, const float* __restrict__ wqk)
{
    __shared__ __align__(16) float As[BM * LDS];
    __shared__ __align__(16) float Bs[BN * LDS];

    const int m0  = blockIdx.x * BM;
    const int n0  = blockIdx.y * BN;
    const int tid = threadIdx.x;
    const int wid = tid >> 5;
    const int wm  = wid & 3;   // 0..3 -> 16 M-rows each
    const int wn  = wid >> 2;  // 0..1 -> 32 N-cols each

    wmma::fragment<wmma::accumulator, 16, 16, 8, float> acc0, acc1;
    wmma::fill_fragment(acc0, 0.0f);
    wmma::fill_fragment(acc1, 0.0f);

    const int lr = tid >> 3;        // 0..31
    const int lc = (tid & 7) * 4;   // 0,4,...,28

    for (int kt = 0; kt < K_; kt += BK) {
        float4 a0 = *(const float4*)(x   + (size_t)(m0 + lr)      * K_ + kt + lc);
        float4 a1 = *(const float4*)(x   + (size_t)(m0 + lr + 32) * K_ + kt + lc);
        float4 b0 = *(const float4*)(wqk + (size_t)(n0 + lr)      * K_ + kt + lc);
        float4 b1 = *(const float4*)(wqk + (size_t)(n0 + lr + 32) * K_ + kt + lc);
        __syncthreads();  // protect smem from previous iteration's consumers
        *(float4*)(As + lr        * LDS + lc) = a0;
        *(float4*)(As + (lr + 32) * LDS + lc) = a1;
        *(float4*)(Bs + lr        * LDS + lc) = b0;
        *(float4*)(Bs + (lr + 32) * LDS + lc) = b1;
        __syncthreads();

        #pragma unroll
        for (int kk = 0; kk < BK; kk += 8) {
            wmma::fragment<wmma::matrix_a, 16, 16, 8, wmma::precision::tf32, wmma::row_major> af;
            wmma::fragment<wmma::matrix_b, 16, 16, 8, wmma::precision::tf32, wmma::col_major> bf0, bf1;
            wmma::load_matrix_sync(af,  As + (wm * 16)      * LDS + kk, LDS);
            wmma::load_matrix_sync(bf0, Bs + (wn * 32)      * LDS + kk, LDS);
            wmma::load_matrix_sync(bf1, Bs + (wn * 32 + 16) * LDS + kk, LDS);
            #pragma unroll
            for (int i = 0; i < af.num_elements;  i++) af.x[i]  = wmma::__float_to_tf32(af.x[i]);
            #pragma unroll
            for (int i = 0; i < bf0.num_elements; i++) bf0.x[i] = wmma::__float_to_tf32(bf0.x[i]);
            #pragma unroll
            for (int i = 0; i < bf1.num_elements; i++) bf1.x[i] = wmma::__float_to_tf32(bf1.x[i]);
            wmma::mma_sync(acc0, af, bf0, acc0);
            wmma::mma_sync(acc1, af, bf1, acc1);
        }
    }

    float* outp = g_qk + (size_t)(m0 + wm * 16) * N_ + n0 + wn * 32;
    wmma::store_matrix_sync(outp,      acc0, N_, wmma::mem_row_major);
    wmma::store_matrix_sync(outp + 16, acc1, N_, wmma::mem_row_major);
}

// ---------------------------------------------------------------------------
// Attention + offsets: one block per pixel
// ---------------------------------------------------------------------------
__device__ __forceinline__ int reflect_idx(int idx, int L)
{
    const int period = 2 * (L - 1);
    int m = idx % period;
    if (m < 0) m += period;
    return (m > L - 1) ? (period - m) : m;
}

__global__ void __launch_bounds__(256) attn_kernel(
    const float* __restrict__ flows, float* __restrict__ out)
{
    const int pix = blockIdx.x;
    const int t   = pix >> 12;
    const int hw  = pix & 4095;
    const int h   = hw >> 6;
    const int w   = hw & 63;

    __shared__ float q_s[512];                 // full q|k row of this pixel (q part used)
    __shared__ float attn_s[HEADS_ * NS_];     // 1176
    __shared__ float fl_s[NS_ * 3];            // 441
    __shared__ int   sdi[3], sdj[3], stp[3], sdt[3];

    const int tid = threadIdx.x;
    const float* qk = g_qk;

    // load q row (first 256 floats of the 512-wide row)
    q_s[tid] = qk[(size_t)pix * 512 + tid];

    if (tid == 0) {
        sdi[0] = 0; sdj[0] = 0; stp[0] = t; sdt[0] = 0;
        const int tp1 = (t + 1 < T_) ? t + 1 : t - 2;
        const int tp2 = (t - 1 >= 0) ? t - 1 : t + 2;
        stp[1] = tp1; sdt[1] = tp1 - t;
        stp[2] = tp2; sdt[2] = tp2 - t;
        // flows layout (1,T,2,2,H,W)
        sdi[1] = (int)rintf(flows[(size_t)((t * 2 + 0) * 2 + 0) * 4096 + hw]);
        sdj[1] = (int)rintf(flows[(size_t)((t * 2 + 0) * 2 + 1) * 4096 + hw]);
        sdi[2] = (int)rintf(flows[(size_t)((t * 2 + 1) * 2 + 0) * 4096 + hw]);
        sdj[2] = (int)rintf(flows[(size_t)((t * 2 + 1) * 2 + 1) * 4096 + hw]);
    }
    __syncthreads();

    // 1176 (key, head) dot products
    for (int task = tid; task < HEADS_ * NS_; task += 256) {
        const int s    = task >> 3;
        const int head = task & 7;
        const int slot = s / 49;
        const int r    = s - slot * 49;
        const int a    = r / 7;
        const int b    = r - a * 7;

        const int li = reflect_idx(h + sdi[slot] + a - 3, H_);
        const int lj = reflect_idx(w + sdj[slot] + b - 3, W_);

        const float* kr = qk + ((size_t)(stp[slot] * 4096 + li * 64 + lj)) * 512
                             + 256 + head * 32;
        const float* qr = q_s + head * 32;

        float acc = 0.0f;
        #pragma unroll
        for (int i = 0; i < 8; i++) {
            const float4 kv = *(const float4*)(kr + i * 4);
            acc += kv.x * qr[i * 4 + 0] + kv.y * qr[i * 4 + 1]
                 + kv.z * qr[i * 4 + 2] + kv.w * qr[i * 4 + 3];
        }
        attn_s[head * NS_ + s] = acc * SCALE_;

        if (head == 0) {
            fl_s[s * 3 + 0] = (float)sdt[slot];
            fl_s[s * 3 + 1] = (float)(li - h);
            fl_s[s * 3 + 2] = (float)(lj - w);
        }
    }
    __syncthreads();

    // attn: (1, HEADS, T, H, W, 147)
    for (int idx = tid; idx < HEADS_ * NS_; idx += 256) {
        const int head = idx / NS_;
        const int s    = idx - head * NS_;
        out[(size_t)((head * T_ + t) * 4096 + hw) * NS_ + s] = attn_s[idx];
    }

    // flows_k: (1, HEADS, T, H, W, 147, 3), appended after attn
    const size_t FBASE = (size_t)HEADS_ * T_ * 4096 * NS_;  // 38,535,168
    for (int idx = tid; idx < HEADS_ * NS_ * 3; idx += 256) {
        const int head = idx / (NS_ * 3);
        const int r    = idx - head * (NS_ * 3);
        out[FBASE + (size_t)((head * T_ + t) * 4096 + hw) * (NS_ * 3) + r] = fl_s[r];
    }
}

// ---------------------------------------------------------------------------
extern "C" void kernel_launch(void* const* d_in, const int* in_sizes, int n_in,
                              void* d_out, int out_size)
{
    const float* x     = (const float*)d_in[0];   // (8,64,64,256)
    const float* flows = (const float*)d_in[1];   // (1,8,2,2,64,64)
    const float* wqk   = (const float*)d_in[2];   // (512,256)
    float* out = (float*)d_out;

    dim3 gg(M_ / BM, N_ / BN);
    gemm_qk_kernel<<<gg, 256>>>(x, wqk);
    attn_kernel<<<NPIX, 256>>>(flows, out);
}

// round 3
// speedup vs baseline: 1.8692x; 1.8692x over previous
#include <cuda_runtime.h>
#include <mma.h>

using namespace nvcuda;

#define T_      8
#define H_      64
#define W_      64
#define C_      256
#define HEADS_  8
#define HD_     32
#define WS_     7
#define NPIX    (T_ * H_ * W_)          // 32768
#define M_      NPIX
#define N_      512
#define K_      256
#define NS_     (3 * WS_ * WS_)         // 147 keys per pixel
#define SCALE_  0.17677669529663687f    // 32^-0.5

// 64 MB scratch for projected q|k rows: [pix][512] (q = cols 0..255, k = 256..511)
__device__ float g_qk[(size_t)NPIX * N_];

// ---------------------------------------------------------------------------
// GEMM: qk[m, n] = sum_k x[m, k] * W_qk[n, k]    (tf32 WMMA, fp32 accum)
// ---------------------------------------------------------------------------
#define BM 64
#define BN 64
#define BK 32
#define LDS 40

__global__ void __launch_bounds__(256) gemm_qk_kernel(
    const float* __restrict__ x, const float* __restrict__ wqk)
{
    __shared__ __align__(16) float As[BM * LDS];
    __shared__ __align__(16) float Bs[BN * LDS];

    const int m0  = blockIdx.x * BM;
    const int n0  = blockIdx.y * BN;
    const int tid = threadIdx.x;
    const int wid = tid >> 5;
    const int wm  = wid & 3;
    const int wn  = wid >> 2;

    wmma::fragment<wmma::accumulator, 16, 16, 8, float> acc0, acc1;
    wmma::fill_fragment(acc0, 0.0f);
    wmma::fill_fragment(acc1, 0.0f);

    const int lr = tid >> 3;
    const int lc = (tid & 7) * 4;

    for (int kt = 0; kt < K_; kt += BK) {
        float4 a0 = *(const float4*)(x   + (size_t)(m0 + lr)      * K_ + kt + lc);
        float4 a1 = *(const float4*)(x   + (size_t)(m0 + lr + 32) * K_ + kt + lc);
        float4 b0 = *(const float4*)(wqk + (size_t)(n0 + lr)      * K_ + kt + lc);
        float4 b1 = *(const float4*)(wqk + (size_t)(n0 + lr + 32) * K_ + kt + lc);
        __syncthreads();
        *(float4*)(As + lr        * LDS + lc) = a0;
        *(float4*)(As + (lr + 32) * LDS + lc) = a1;
        *(float4*)(Bs + lr        * LDS + lc) = b0;
        *(float4*)(Bs + (lr + 32) * LDS + lc) = b1;
        __syncthreads();

        #pragma unroll
        for (int kk = 0; kk < BK; kk += 8) {
            wmma::fragment<wmma::matrix_a, 16, 16, 8, wmma::precision::tf32, wmma::row_major> af;
            wmma::fragment<wmma::matrix_b, 16, 16, 8, wmma::precision::tf32, wmma::col_major> bf0, bf1;
            wmma::load_matrix_sync(af,  As + (wm * 16)      * LDS + kk, LDS);
            wmma::load_matrix_sync(bf0, Bs + (wn * 32)      * LDS + kk, LDS);
            wmma::load_matrix_sync(bf1, Bs + (wn * 32 + 16) * LDS + kk, LDS);
            #pragma unroll
            for (int i = 0; i < af.num_elements;  i++) af.x[i]  = wmma::__float_to_tf32(af.x[i]);
            #pragma unroll
            for (int i = 0; i < bf0.num_elements; i++) bf0.x[i] = wmma::__float_to_tf32(bf0.x[i]);
            #pragma unroll
            for (int i = 0; i < bf1.num_elements; i++) bf1.x[i] = wmma::__float_to_tf32(bf1.x[i]);
            wmma::mma_sync(acc0, af, bf0, acc0);
            wmma::mma_sync(acc1, af, bf1, acc1);
        }
    }

    float* outp = g_qk + (size_t)(m0 + wm * 16) * N_ + n0 + wn * 32;
    wmma::store_matrix_sync(outp,      acc0, N_, wmma::mem_row_major);
    wmma::store_matrix_sync(outp + 16, acc1, N_, wmma::mem_row_major);
}

// ---------------------------------------------------------------------------
// Attention: one block per pixel, one WARP per key (coalesced k-row loads)
// ---------------------------------------------------------------------------
__device__ __forceinline__ int reflect_idx(int idx, int L)
{
    const int period = 2 * (L - 1);
    int m = idx % period;
    if (m < 0) m += period;
    return (m > L - 1) ? (period - m) : m;
}

__global__ void __launch_bounds__(256) attn_kernel(
    const float* __restrict__ flows, float* __restrict__ out)
{
    const int pix = blockIdx.x;
    const int t   = pix >> 12;
    const int hw  = pix & 4095;
    const int h   = hw >> 6;
    const int w   = hw & 63;

    __shared__ float q_s[256];
    __shared__ float attn_s[HEADS_ * NS_];     // 1176
    __shared__ float fl_s[NS_ * 3];            // 441
    __shared__ int   sdi[3], sdj[3], stp[3], sdt[3];

    const int tid  = threadIdx.x;
    const int warp = tid >> 5;
    const int lane = tid & 31;
    const float* qk = g_qk;

    // q row of this pixel (first 256 of 512-wide row)
    q_s[tid] = qk[(size_t)pix * 512 + tid];

    if (tid == 0) {
        sdi[0] = 0; sdj[0] = 0; stp[0] = t; sdt[0] = 0;
        const int tp1 = (t + 1 < T_) ? t + 1 : t - 2;
        const int tp2 = (t - 1 >= 0) ? t - 1 : t + 2;
        stp[1] = tp1; sdt[1] = tp1 - t;
        stp[2] = tp2; sdt[2] = tp2 - t;
        sdi[1] = (int)rintf(flows[(size_t)((t * 2 + 0) * 2 + 0) * 4096 + hw]);
        sdj[1] = (int)rintf(flows[(size_t)((t * 2 + 0) * 2 + 1) * 4096 + hw]);
        sdi[2] = (int)rintf(flows[(size_t)((t * 2 + 1) * 2 + 0) * 4096 + hw]);
        sdj[2] = (int)rintf(flows[(size_t)((t * 2 + 1) * 2 + 1) * 4096 + hw]);
    }
    __syncthreads();

    // Hoist q fragments: lane i covers head i/8 (low) and head 4+i/8 (high)
    const float4 qv0 = *(const float4*)(q_s + lane * 4);         // floats [0,128)
    const float4 qv1 = *(const float4*)(q_s + 128 + lane * 4);   // floats [128,256)

    // one warp per key; 8 warps stride over 147 keys
    for (int s = warp; s < NS_; s += 8) {
        const int slot = s / 49;
        const int r    = s - slot * 49;
        const int a    = r / 7;
        const int b    = r - a * 7;

        const int li = reflect_idx(h + sdi[slot] + a - 3, H_);
        const int lj = reflect_idx(w + sdj[slot] + b - 3, W_);

        const float* kr = qk + ((size_t)(stp[slot] * 4096 + li * 64 + lj)) * 512 + 256;

        // fully coalesced: 32 lanes x 16B contiguous, twice
        const float4 kv0 = *(const float4*)(kr + lane * 4);
        const float4 kv1 = *(const float4*)(kr + 128 + lane * 4);

        float p0 = kv0.x * qv0.x + kv0.y * qv0.y + kv0.z * qv0.z + kv0.w * qv0.w;
        float p1 = kv1.x * qv1.x + kv1.y * qv1.y + kv1.z * qv1.z + kv1.w * qv1.w;

        // reduce within 8-lane head groups
        p0 += __shfl_xor_sync(0xffffffffu, p0, 1);
        p1 += __shfl_xor_sync(0xffffffffu, p1, 1);
        p0 += __shfl_xor_sync(0xffffffffu, p0, 2);
        p1 += __shfl_xor_sync(0xffffffffu, p1, 2);
        p0 += __shfl_xor_sync(0xffffffffu, p0, 4);
        p1 += __shfl_xor_sync(0xffffffffu, p1, 4);

        if ((lane & 7) == 0) {
            const int hd = lane >> 3;            // 0..3
            attn_s[hd * NS_ + s]       = p0 * SCALE_;
            attn_s[(hd + 4) * NS_ + s] = p1 * SCALE_;
        }
        if (lane == 0) {
            fl_s[s * 3 + 0] = (float)sdt[slot];
            fl_s[s * 3 + 1] = (float)(li - h);
            fl_s[s * 3 + 2] = (float)(lj - w);
        }
    }
    __syncthreads();

    // attn: (1, HEADS, T, H, W, 147)
    for (int idx = tid; idx < HEADS_ * NS_; idx += 256) {
        const int head = idx / NS_;
        const int s    = idx - head * NS_;
        out[(size_t)((head * T_ + t) * 4096 + hw) * NS_ + s] = attn_s[idx];
    }

    // flows_k: (1, HEADS, T, H, W, 147, 3), appended after attn
    const size_t FBASE = (size_t)HEADS_ * T_ * 4096 * NS_;  // 38,535,168
    for (int idx = tid; idx < HEADS_ * NS_ * 3; idx += 256) {
        const int head = idx / (NS_ * 3);
        const int r    = idx - head * (NS_ * 3);
        out[FBASE + (size_t)((head * T_ + t) * 4096 + hw) * (NS_ * 3) + r] = fl_s[r];
    }
}

// ---------------------------------------------------------------------------
extern "C" void kernel_launch(void* const* d_in, const int* in_sizes, int n_in,
                              void* d_out, int out_size)
{
    const float* x     = (const float*)d_in[0];   // (8,64,64,256)
    const float* flows = (const float*)d_in[1];   // (1,8,2,2,64,64)
    const float* wqk   = (const float*)d_in[2];   // (512,256)
    float* out = (float*)d_out;

    dim3 gg(M_ / BM, N_ / BN);
    gemm_qk_kernel<<<gg, 256>>>(x, wqk);
    attn_kernel<<<NPIX, 256>>>(flows, out);
}

// round 4
// speedup vs baseline: 3.7480x; 2.0051x over previous
#include <cuda_runtime.h>
#include <cuda_fp16.h>
#include <mma.h>

using namespace nvcuda;

#define T_      8
#define H_      64
#define W_      64
#define C_      256
#define HEADS_  8
#define HD_     32
#define WS_     7
#define NPIX    (T_ * H_ * W_)          // 32768
#define M_      NPIX
#define N_      512
#define K_      256
#define NS_     (3 * WS_ * WS_)         // 147
#define SCALE_  0.17677669529663687f    // 32^-0.5

// scratch: q fp32 [pix][256], k fp16 [pix][256]
__device__ float  g_q [(size_t)NPIX * 256];
__device__ __half g_kh[(size_t)NPIX * 256];

// ---------------------------------------------------------------------------
// packed f32x2 helpers
// ---------------------------------------------------------------------------
__device__ __forceinline__ unsigned long long pk(float x, float y)
{
    unsigned long long r;
    asm("mov.b64 %0, {%1, %2};" : "=l"(r) : "f"(x), "f"(y));
    return r;
}
__device__ __forceinline__ float2 upk(unsigned long long v)
{
    float2 r;
    asm("mov.b64 {%0, %1}, %2;" : "=f"(r.x), "=f"(r.y) : "l"(v));
    return r;
}
__device__ __forceinline__ void fma2(unsigned long long& acc,
                                     unsigned long long a, unsigned long long b)
{
    asm("fma.rn.f32x2 %0, %1, %2, %0;" : "+l"(acc) : "l"(a), "l"(b));
}

// ---------------------------------------------------------------------------
// GEMM: qk[m, n] = sum_k x[m, k] * W_qk[n, k]   (tf32 WMMA, fused epilogue)
// ---------------------------------------------------------------------------
#define BM 64
#define BN 64
#define BK 32
#define LDS 40

__global__ void __launch_bounds__(256) gemm_qk_kernel(
    const float* __restrict__ x, const float* __restrict__ wqk)
{
    __shared__ __align__(16) float S[5120];
    float* As = S;          // 64 x 40
    float* Bs = S + 2560;   // 64 x 40

    const int m0  = blockIdx.x * BM;
    const int n0  = blockIdx.y * BN;
    const int tid = threadIdx.x;
    const int wid = tid >> 5;
    const int lane = tid & 31;
    const int wm  = wid & 3;
    const int wn  = wid >> 2;

    wmma::fragment<wmma::accumulator, 16, 16, 8, float> acc0, acc1;
    wmma::fill_fragment(acc0, 0.0f);
    wmma::fill_fragment(acc1, 0.0f);

    const int lr = tid >> 3;
    const int lc = (tid & 7) * 4;

    for (int kt = 0; kt < K_; kt += BK) {
        float4 a0 = *(const float4*)(x   + (size_t)(m0 + lr)      * K_ + kt + lc);
        float4 a1 = *(const float4*)(x   + (size_t)(m0 + lr + 32) * K_ + kt + lc);
        float4 b0 = *(const float4*)(wqk + (size_t)(n0 + lr)      * K_ + kt + lc);
        float4 b1 = *(const float4*)(wqk + (size_t)(n0 + lr + 32) * K_ + kt + lc);
        // convert to tf32 precision once, at staging
        a0.x = wmma::__float_to_tf32(a0.x); a0.y = wmma::__float_to_tf32(a0.y);
        a0.z = wmma::__float_to_tf32(a0.z); a0.w = wmma::__float_to_tf32(a0.w);
        a1.x = wmma::__float_to_tf32(a1.x); a1.y = wmma::__float_to_tf32(a1.y);
        a1.z = wmma::__float_to_tf32(a1.z); a1.w = wmma::__float_to_tf32(a1.w);
        b0.x = wmma::__float_to_tf32(b0.x); b0.y = wmma::__float_to_tf32(b0.y);
        b0.z = wmma::__float_to_tf32(b0.z); b0.w = wmma::__float_to_tf32(b0.w);
        b1.x = wmma::__float_to_tf32(b1.x); b1.y = wmma::__float_to_tf32(b1.y);
        b1.z = wmma::__float_to_tf32(b1.z); b1.w = wmma::__float_to_tf32(b1.w);
        __syncthreads();
        *(float4*)(As + lr        * LDS + lc) = a0;
        *(float4*)(As + (lr + 32) * LDS + lc) = a1;
        *(float4*)(Bs + lr        * LDS + lc) = b0;
        *(float4*)(Bs + (lr + 32) * LDS + lc) = b1;
        __syncthreads();

        #pragma unroll
        for (int kk = 0; kk < BK; kk += 8) {
            wmma::fragment<wmma::matrix_a, 16, 16, 8, wmma::precision::tf32, wmma::row_major> af;
            wmma::fragment<wmma::matrix_b, 16, 16, 8, wmma::precision::tf32, wmma::col_major> bf0, bf1;
            wmma::load_matrix_sync(af,  As + (wm * 16)      * LDS + kk, LDS);
            wmma::load_matrix_sync(bf0, Bs + (wn * 32)      * LDS + kk, LDS);
            wmma::load_matrix_sync(bf1, Bs + (wn * 32 + 16) * LDS + kk, LDS);
            wmma::mma_sync(acc0, af, bf0, acc0);
            wmma::mma_sync(acc1, af, bf1, acc1);
        }
    }

    // epilogue: restage through smem, write q fp32 / k fp16
    __syncthreads();
    float* wbuf = S + wid * 576;   // 16 rows x ld 36
    wmma::store_matrix_sync(wbuf,      acc0, 36, wmma::mem_row_major);
    wmma::store_matrix_sync(wbuf + 16, acc1, 36, wmma::mem_row_major);
    __syncwarp();

    const int row  = lane >> 1;
    const int colh = (lane & 1) << 4;
    const float* src = wbuf + row * 36 + colh;
    const float4 v0 = *(const float4*)(src);
    const float4 v1 = *(const float4*)(src + 4);
    const float4 v2 = *(const float4*)(src + 8);
    const float4 v3 = *(const float4*)(src + 12);
    const int gr = m0 + wm * 16 + row;
    const int gc = n0 + wn * 32 + colh;

    if (n0 < 256) {
        float* dst = g_q + (size_t)gr * 256 + gc;
        *(float4*)(dst)      = v0;
        *(float4*)(dst + 4)  = v1;
        *(float4*)(dst + 8)  = v2;
        *(float4*)(dst + 12) = v3;
    } else {
        __half2 h0 = __floats2half2_rn(v0.x, v0.y);
        __half2 h1 = __floats2half2_rn(v0.z, v0.w);
        __half2 h2 = __floats2half2_rn(v1.x, v1.y);
        __half2 h3 = __floats2half2_rn(v1.z, v1.w);
        __half2 h4 = __floats2half2_rn(v2.x, v2.y);
        __half2 h5 = __floats2half2_rn(v2.z, v2.w);
        __half2 h6 = __floats2half2_rn(v3.x, v3.y);
        __half2 h7 = __floats2half2_rn(v3.z, v3.w);
        __half* dst = g_kh + (size_t)gr * 256 + (gc - 256);
        uint4 o0, o1;
        o0.x = *(unsigned*)&h0; o0.y = *(unsigned*)&h1;
        o0.z = *(unsigned*)&h2; o0.w = *(unsigned*)&h3;
        o1.x = *(unsigned*)&h4; o1.y = *(unsigned*)&h5;
        o1.z = *(unsigned*)&h6; o1.w = *(unsigned*)&h7;
        *(uint4*)(dst)     = o0;
        *(uint4*)(dst + 8) = o1;
    }
}

// ---------------------------------------------------------------------------
// Attention: one block per pixel, one warp per key, all index math hoisted
// ---------------------------------------------------------------------------
__device__ __forceinline__ int reflect_idx(int idx, int L)
{
    const int period = 2 * (L - 1);
    int m = idx % period;
    if (m < 0) m += period;
    return (m > L - 1) ? (period - m) : m;
}

__global__ void __launch_bounds__(256) attn_kernel(
    const float* __restrict__ flows, float* __restrict__ out)
{
    const int pix = blockIdx.x;
    const int t   = pix >> 12;
    const int hw  = pix & 4095;
    const int h   = hw >> 6;
    const int w   = hw & 63;

    __shared__ int   off_s[NS_];           // flattened k-row index per key
    __shared__ float fl_s[NS_ * 3];        // 441
    __shared__ float attn_s[HEADS_ * NS_]; // 1176
    __shared__ int   s_fl[4];

    const int tid  = threadIdx.x;
    const int warp = tid >> 5;
    const int lane = tid & 31;

    if (tid < 4) {
        const int p_ = tid >> 1, c_ = tid & 1;
        s_fl[tid] = (int)rintf(flows[(size_t)((t * 2 + p_) * 2 + c_) * 4096 + hw]);
    }

    // q fragment for this lane (elements 8*lane .. 8*lane+7), pre-scaled & packed
    const float4 qa = *(const float4*)(g_q + (size_t)pix * 256 + lane * 8);
    const float4 qb = *(const float4*)(g_q + (size_t)pix * 256 + lane * 8 + 4);
    const unsigned long long q0 = pk(qa.x * SCALE_, qa.y * SCALE_);
    const unsigned long long q1 = pk(qa.z * SCALE_, qa.w * SCALE_);
    const unsigned long long q2 = pk(qb.x * SCALE_, qb.y * SCALE_);
    const unsigned long long q3 = pk(qb.z * SCALE_, qb.w * SCALE_);

    __syncthreads();   // s_fl ready

    if (tid < NS_) {
        const int slot = (tid >= 49) + (tid >= 98);
        const int r    = tid - slot * 49;
        const int a    = r / 7;
        const int b    = r - a * 7;
        int di = 0, dj = 0, tp = t;
        if (slot == 1) { tp = (t + 1 < T_) ? t + 1 : t - 2; di = s_fl[0]; dj = s_fl[1]; }
        if (slot == 2) { tp = (t - 1 >= 0) ? t - 1 : t + 2; di = s_fl[2]; dj = s_fl[3]; }
        const int li = reflect_idx(h + di + a - 3, H_);
        const int lj = reflect_idx(w + dj + b - 3, W_);
        off_s[tid] = (tp << 12) + li * 64 + lj;
        fl_s[tid * 3 + 0] = (float)(tp - t);
        fl_s[tid * 3 + 1] = (float)(li - h);
        fl_s[tid * 3 + 2] = (float)(lj - w);
    }
    __syncthreads();

    #pragma unroll 2
    for (int s = warp; s < NS_; s += 8) {
        const int off = off_s[s];                      // LDS broadcast
        const uint4 kv = *(const uint4*)(g_kh + (((size_t)off) << 8) + lane * 8);
        const __half2* hp = (const __half2*)&kv;
        const float2 f0 = __half22float2(hp[0]);
        const float2 f1 = __half22float2(hp[1]);
        const float2 f2 = __half22float2(hp[2]);
        const float2 f3 = __half22float2(hp[3]);
        unsigned long long acc = 0ull;                 // (+0.0f, +0.0f)
        fma2(acc, pk(f0.x, f0.y), q0);
        fma2(acc, pk(f1.x, f1.y), q1);
        fma2(acc, pk(f2.x, f2.y), q2);
        fma2(acc, pk(f3.x, f3.y), q3);
        const float2 pr = upk(acc);
        float p = pr.x + pr.y;
        p += __shfl_xor_sync(0xffffffffu, p, 1);
        p += __shfl_xor_sync(0xffffffffu, p, 2);
        if ((lane & 3) == 0)
            attn_s[(lane >> 2) * NS_ + s] = p;         // head = lane>>2
    }
    __syncthreads();

    // attn: (1, HEADS, T, H, W, 147)
    #pragma unroll
    for (int head = 0; head < HEADS_; head++) {
        if (tid < NS_)
            out[(size_t)((head * T_ + t) * 4096 + hw) * NS_ + tid] = attn_s[head * NS_ + tid];
    }

    // flows_k: (1, HEADS, T, H, W, 147, 3)
    const size_t FBASE = (size_t)HEADS_ * T_ * 4096 * NS_;  // 38,535,168
    #pragma unroll
    for (int head = 0; head < HEADS_; head++) {
        for (int idx = tid; idx < NS_ * 3; idx += 256)
            out[FBASE + (size_t)((head * T_ + t) * 4096 + hw) * (NS_ * 3) + idx] = fl_s[idx];
    }
}

// ---------------------------------------------------------------------------
extern "C" void kernel_launch(void* const* d_in, const int* in_sizes, int n_in,
                              void* d_out, int out_size)
{
    const float* x     = (const float*)d_in[0];   // (8,64,64,256)
    const float* flows = (const float*)d_in[1];   // (1,8,2,2,64,64)
    const float* wqk   = (const float*)d_in[2];   // (512,256)
    float* out = (float*)d_out;

    dim3 gg(M_ / BM, N_ / BN);
    gemm_qk_kernel<<<gg, 256>>>(x, wqk);
    attn_kernel<<<NPIX, 256>>>(flows, out);
}